// round 6
// baseline (speedup 1.0000x reference)
#include <cuda_runtime.h>
#include <math.h>

#define HW 4096
#define BATCH 2

typedef unsigned long long ull;

// Scratch (device globals — no allocation allowed)
__device__ float g_qkv[BATCH * 288 * HW];  // QKV; later reused as out-proj partial slabs
__device__ float g_att[BATCH * 288 * HW];  // channel = head*72 + range*24 + d

// ---------------------------------------------------------------------------
// f32x2 helpers
// ---------------------------------------------------------------------------
__device__ __forceinline__ ull pk2(float a) {
    ull r; asm("mov.b64 %0, {%1,%1};" : "=l"(r) : "f"(a)); return r;
}
__device__ __forceinline__ ull pkpair(float lo, float hi) {
    ull r; asm("mov.b64 %0, {%1,%2};" : "=l"(r) : "f"(lo), "f"(hi)); return r;
}
__device__ __forceinline__ ull ffma2(ull a, ull b, ull c) {
    ull d; asm("fma.rn.f32x2 %0, %1, %2, %3;" : "=l"(d) : "l"(a), "l"(b), "l"(c)); return d;
}
__device__ __forceinline__ void upk(ull v, float& lo, float& hi) {
    asm("mov.b64 {%0,%1}, %2;" : "=f"(lo), "=f"(hi) : "l"(v));
}

// ---------------------------------------------------------------------------
// GEMM (f32x2): C[m][pix] = [bias[m] +] sum_{k chunk} W[m][k] * X[k][pix]
// BM=96, BN=64, BK=16, 192 threads, TM=4, TN=8.
// PARTIAL: z selects K-chunk, raw store. Else z=0 (plain GEMM + bias).
// ---------------------------------------------------------------------------
#define WSTR 100

template <int KTOT, int KCHUNK, bool PARTIAL>
__global__ __launch_bounds__(192) void gemm_k(
    const float* __restrict__ X, long xstride, long cstride,
    const float* __restrict__ W, const float* __restrict__ bias,
    float* c0, float* c1)
{
    const int z = blockIdx.z;
    float* __restrict__ C = (PARTIAL && z == 1) ? c1 : c0;
    const int kbeg = PARTIAL ? z * KCHUNK : 0;
    C += (long)blockIdx.y * cstride;
    const float* __restrict__ Xb = X + (long)blockIdx.y * xstride;

    __shared__ float Ws[16][WSTR];
    __shared__ float Xs[16][64];

    const int tid = threadIdx.x;
    const int tx = tid & 7;      // n: 8 cols each
    const int ty = tid >> 3;     // m: 0..23, 4 rows each
    const int n0 = blockIdx.x * 64;

    ull acc[4][4] = {};

    for (int k0 = kbeg; k0 < kbeg + KCHUNK; k0 += 16) {
        // W tile 96x16 -> Ws[kk][m] (transposed); 384 float4 / 192 thr
        #pragma unroll
        for (int i = 0; i < 2; i++) {
            int idx = tid + i * 192;
            int m = idx >> 2, kq = (idx & 3) * 4;
            float4 w = *(const float4*)&W[(long)m * KTOT + k0 + kq];
            Ws[kq + 0][m] = w.x;
            Ws[kq + 1][m] = w.y;
            Ws[kq + 2][m] = w.z;
            Ws[kq + 3][m] = w.w;
        }
        // X tile 16x64; 256 float4 / 192 thr
        for (int idx = tid; idx < 256; idx += 192) {
            int r = idx >> 4, c = (idx & 15) * 4;
            *(float4*)&Xs[r][c] = *(const float4*)&Xb[(long)(k0 + r) * HW + n0 + c];
        }
        __syncthreads();

        #pragma unroll
        for (int kk = 0; kk < 16; kk++) {
            float4 a4 = *(float4*)&Ws[kk][ty * 4];
            ull ad[4] = {pk2(a4.x), pk2(a4.y), pk2(a4.z), pk2(a4.w)};
            ulonglong2 x0 = *(ulonglong2*)&Xs[kk][tx * 8];
            ulonglong2 x1 = *(ulonglong2*)&Xs[kk][tx * 8 + 4];
            ull bq[4] = {x0.x, x0.y, x1.x, x1.y};
            #pragma unroll
            for (int i = 0; i < 4; i++)
                #pragma unroll
                for (int j = 0; j < 4; j++)
                    acc[i][j] = ffma2(ad[i], bq[j], acc[i][j]);
        }
        __syncthreads();
    }

    #pragma unroll
    for (int i = 0; i < 4; i++) {
        int m = ty * 4 + i;
        float bv = PARTIAL ? 0.f : bias[m];
        float4 o0, o1;
        upk(acc[i][0], o0.x, o0.y);
        upk(acc[i][1], o0.z, o0.w);
        upk(acc[i][2], o1.x, o1.y);
        upk(acc[i][3], o1.z, o1.w);
        o0.x += bv; o0.y += bv; o0.z += bv; o0.w += bv;
        o1.x += bv; o1.y += bv; o1.z += bv; o1.w += bv;
        float* cp = &C[(long)m * HW + n0 + tx * 8];
        *(float4*)cp = o0;
        *(float4*)(cp + 4) = o1;
    }
}

// out = p0 + p1 + bias[m]; 4 float4 per thread for MLP
__global__ __launch_bounds__(256) void finish_out(
    const float* __restrict__ p0, const float* __restrict__ p1,
    const float* __restrict__ bo, float* __restrict__ out)
{
    int t = blockIdx.x * 256 + threadIdx.x;   // < 49152
    float4 a[4], c[4];
    #pragma unroll
    for (int i = 0; i < 4; i++) {
        int idx = t + i * 49152;
        a[i] = ((const float4*)p0)[idx];
        c[i] = ((const float4*)p1)[idx];
    }
    #pragma unroll
    for (int i = 0; i < 4; i++) {
        int idx = t + i * 49152;
        int m = (idx >> 10) % 96;
        float bv = bo[m];
        float4 o;
        o.x = a[i].x + c[i].x + bv;
        o.y = a[i].y + c[i].y + bv;
        o.z = a[i].z + c[i].z + bv;
        o.w = a[i].w + c[i].w + bv;
        ((float4*)out)[idx] = o;
    }
}

// ---------------------------------------------------------------------------
// Attention v4: 8x16 pixel tile per CTA; 256 threads = 64 x-adjacent pixel
// PAIRS x 4 channel-quarter lanes (dq = tid&3 handles channels dq*6..dq*6+5).
// Score partial-dots reduced across the 4 lanes with shfl.xor (bitwise
// deterministic); exp duplicated per lane; V accumulated per-lane channels.
// Each K/V site read once per lane-quartet => same total LDS as pixel-pair
// sharing, but accumulators are only 18 ull/thread (no spills).
// Halo 18x26, PSTR=26 words with channel-interleaved layout:
//   channel d (q=d/6, r=d%6) -> word (r>>1)*8 + q*2 + (r&1)
// so lane addresses differ by 2 words => every LDS.64 is <=2-way (free).
// 97.3 KB smem -> 2 CTAs/SM (16 warps); grid 256 CTAs = one wave.
// ---------------------------------------------------------------------------
#define PSTR 26
#define HROWS 18
#define HCOLS 26
#define HPX (HROWS * HCOLS)              // 468
#define ATTN_SMEM (2 * HPX * PSTR * 4)   // 97344 B

__global__ __launch_bounds__(256, 2) void attn_kernel()
{
    extern __shared__ float sh[];
    float* Ksh = sh;
    float* Vsh = sh + HPX * PSTR;

    const int head = blockIdx.y;
    const int b = blockIdx.z;
    const int th = (blockIdx.x >> 2) * 8;     // 8 y-tiles
    const int tw = (blockIdx.x & 3) * 16;     // 4 x-tiles
    const int h0 = th - 5, w0 = tw - 5;

    const float* base = g_qkv + (long)b * 288 * HW;
    const float* Kg = base + (96 + head * 24) * HW;
    const float* Vg = base + (192 + head * 24) * HW;

    const int tid = threadIdx.x;

    // ---- halo load: <=2 sites per thread, channel-interleaved layout ----
    {
        int po[2]; int gi[2]; bool ok[2]; int cnt = 0;
        for (int p = tid; p < HPX; p += 256) {
            int py = p / HCOLS, px = p - py * HCOLS;
            int gy = h0 + py, gx = w0 + px;
            po[cnt] = p * PSTR;
            ok[cnt] = ((unsigned)gy < 64u) && ((unsigned)gx < 64u);
            gi[cnt] = ok[cnt] ? (gy * 64 + gx) : 0;
            cnt++;
        }
        #pragma unroll
        for (int d = 0; d < 24; d++) {
            const int w = ((d % 6) >> 1) * 8 + (d / 6) * 2 + (d & 1);
            long doff = (long)d * HW;
            #pragma unroll
            for (int n = 0; n < 2; n++) {
                if (n < cnt) {
                    float kv = ok[n] ? Kg[doff + gi[n]] : 0.f;
                    float vv = ok[n] ? Vg[doff + gi[n]] : 0.f;
                    Ksh[po[n] + w] = kv;
                    Vsh[po[n] + w] = vv;
                }
            }
        }
    }
    __syncthreads();

    const int pid = tid >> 2;             // pair id 0..63
    const int dq  = tid & 3;              // channel quarter
    const int py  = pid >> 3;             // 0..7
    const int px0 = (pid & 7) * 2;        // pixel A col; B = px0+1

    // Q for both pixels, channels dq*6 .. dq*6+5, 1/sqrt(24) folded in
    const float* QgA = g_qkv + ((long)b * 288 + head * 24 + dq * 6) * HW
                       + (th + py) * 64 + (tw + px0);
    ull q2A[3], q2B[3];
    #pragma unroll
    for (int j = 0; j < 3; j++) {
        const float sc = 0.2041241452319315f;
        float a0 = QgA[(long)(2 * j) * HW] * sc;
        float a1 = QgA[(long)(2 * j + 1) * HW] * sc;
        float b0 = QgA[(long)(2 * j) * HW + 1] * sc;
        float b1 = QgA[(long)(2 * j + 1) * HW + 1] * sc;
        q2A[j] = pkpair(a0, a1);
        q2B[j] = pkpair(b0, b1);
    }

    ull aA7[3] = {}, aA9[3] = {}, aA11[3] = {};
    ull aB7[3] = {}, aB9[3] = {}, aB11[3] = {};
    float lA7 = 0.f, lA9 = 0.f, lA11 = 0.f;
    float lB7 = 0.f, lB9 = 0.f, lB11 = 0.f;
    const int cbase = (py + 5) * HCOLS + (px0 + 5);

#define SITE2(POFF, AA, LA, AB, LB) { \
    const ull* kp = (const ull*)(Ksh + (cbase + (POFF)) * PSTR); \
    const ull* vp = (const ull*)(Vsh + (cbase + (POFF)) * PSTR); \
    ull sa = 0ULL, ta = 0ULL; \
    _Pragma("unroll") for (int j = 0; j < 3; j++) { \
        ull kv = kp[4 * j + dq]; \
        sa = ffma2(q2A[j], kv, sa); ta = ffma2(q2B[j], kv, ta); } \
    float x0, x1, sA, sB; \
    upk(sa, x0, x1); sA = x0 + x1; \
    upk(ta, x0, x1); sB = x0 + x1; \
    sA += __shfl_xor_sync(0xffffffffu, sA, 1); \
    sA += __shfl_xor_sync(0xffffffffu, sA, 2); \
    sB += __shfl_xor_sync(0xffffffffu, sB, 1); \
    sB += __shfl_xor_sync(0xffffffffu, sB, 2); \
    float eA = __expf(sA), eB = __expf(sB); \
    LA += eA; LB += eB; \
    ull pA = pk2(eA), pB = pk2(eB); \
    _Pragma("unroll") for (int j = 0; j < 3; j++) { \
        ull vv = vp[4 * j + dq]; \
        AA[j] = ffma2(pA, vv, AA[j]); AB[j] = ffma2(pB, vv, AB[j]); } \
}

#define SITE1(POFF, Q2, AC, L) { \
    const ull* kp = (const ull*)(Ksh + (cbase + (POFF)) * PSTR); \
    const ull* vp = (const ull*)(Vsh + (cbase + (POFF)) * PSTR); \
    ull sa = 0ULL; \
    _Pragma("unroll") for (int j = 0; j < 3; j++) \
        sa = ffma2(Q2[j], kp[4 * j + dq], sa); \
    float x0, x1, s; \
    upk(sa, x0, x1); s = x0 + x1; \
    s += __shfl_xor_sync(0xffffffffu, s, 1); \
    s += __shfl_xor_sync(0xffffffffu, s, 2); \
    float e = __expf(s); \
    L += e; ull pe = pk2(e); \
    _Pragma("unroll") for (int j = 0; j < 3; j++) \
        AC[j] = ffma2(pe, vp[4 * j + dq], AC[j]); \
}

    // |dy| == 5: everything ring-11
#define ROW5(DY) { \
    SITE1((DY) * HCOLS - 5, q2A, aA11, lA11) \
    _Pragma("unroll 2") for (int dx = -4; dx <= 5; dx++) { SITE2((DY) * HCOLS + dx, aA11, lA11, aB11, lB11) } \
    SITE1((DY) * HCOLS + 6, q2B, aB11, lB11) \
}
    // |dy| == 4
#define ROW4(DY) { \
    SITE1((DY) * HCOLS - 5, q2A, aA11, lA11) \
    SITE2((DY) * HCOLS - 4, aA9, lA9, aB11, lB11) \
    _Pragma("unroll 2") for (int dx = -3; dx <= 4; dx++) { SITE2((DY) * HCOLS + dx, aA9, lA9, aB9, lB9) } \
    SITE2((DY) * HCOLS + 5, aA11, lA11, aB9, lB9) \
    SITE1((DY) * HCOLS + 6, q2B, aB11, lB11) \
}
    // |dy| <= 3
#define ROW3(DY) { \
    SITE1((DY) * HCOLS - 5, q2A, aA11, lA11) \
    SITE2((DY) * HCOLS - 4, aA9, lA9, aB11, lB11) \
    SITE2((DY) * HCOLS - 3, aA7, lA7, aB9, lB9) \
    _Pragma("unroll 2") for (int dx = -2; dx <= 3; dx++) { SITE2((DY) * HCOLS + dx, aA7, lA7, aB7, lB7) } \
    SITE2((DY) * HCOLS + 4, aA9, lA9, aB7, lB7) \
    SITE2((DY) * HCOLS + 5, aA11, lA11, aB9, lB9) \
    SITE1((DY) * HCOLS + 6, q2B, aB11, lB11) \
}

    ROW5(-5)
    ROW4(-4)
    #pragma unroll 1
    for (int dy = -3; dy <= 3; dy++) { ROW3(dy) }
    ROW4(4)
    ROW5(5)

#undef SITE2
#undef SITE1
#undef ROW5
#undef ROW4
#undef ROW3

    // ---- epilogue: no cross-thread reduction needed (l's identical in all
    //      4 lanes; each lane owns its 6 channels) ----
    float* A = g_att + ((long)b * 288 + head * 72 + dq * 6) * HW
               + (th + py) * 64 + (tw + px0);

    {   // pixel A
        const float r7  = __fdividef(1.f, lA7);
        const float t9  = lA7 + lA9;
        const float r9  = __fdividef(1.f, t9);
        const float r11 = __fdividef(1.f, t9 + lA11);
        #pragma unroll
        for (int j = 0; j < 3; j++) {
            float p70, p71, p90, p91, pb0, pb1;
            upk(aA7[j], p70, p71);
            upk(aA9[j], p90, p91);
            upk(aA11[j], pb0, pb1);
            float s90 = p70 + p90, s91 = p71 + p91;
            float sb0 = s90 + pb0, sb1 = s91 + pb1;
            A[(long)(2 * j) * HW]          = p70 * r7;
            A[(long)(2 * j + 1) * HW]      = p71 * r7;
            A[(long)(24 + 2 * j) * HW]     = s90 * r9;
            A[(long)(24 + 2 * j + 1) * HW] = s91 * r9;
            A[(long)(48 + 2 * j) * HW]     = sb0 * r11;
            A[(long)(48 + 2 * j + 1) * HW] = sb1 * r11;
        }
    }
    {   // pixel B (col +1)
        const float r7  = __fdividef(1.f, lB7);
        const float t9  = lB7 + lB9;
        const float r9  = __fdividef(1.f, t9);
        const float r11 = __fdividef(1.f, t9 + lB11);
        #pragma unroll
        for (int j = 0; j < 3; j++) {
            float p70, p71, p90, p91, pb0, pb1;
            upk(aB7[j], p70, p71);
            upk(aB9[j], p90, p91);
            upk(aB11[j], pb0, pb1);
            float s90 = p70 + p90, s91 = p71 + p91;
            float sb0 = s90 + pb0, sb1 = s91 + pb1;
            A[(long)(2 * j) * HW + 1]          = p70 * r7;
            A[(long)(2 * j + 1) * HW + 1]      = p71 * r7;
            A[(long)(24 + 2 * j) * HW + 1]     = s90 * r9;
            A[(long)(24 + 2 * j + 1) * HW + 1] = s91 * r9;
            A[(long)(48 + 2 * j) * HW + 1]     = sb0 * r11;
            A[(long)(48 + 2 * j + 1) * HW + 1] = sb1 * r11;
        }
    }
}

// ---------------------------------------------------------------------------
extern "C" void kernel_launch(void* const* d_in, const int* in_sizes, int n_in,
                              void* d_out, int out_size)
{
    const float* x  = (const float*)d_in[0];
    const float* wq = (const float*)d_in[1];
    const float* bq = (const float*)d_in[2];
    const float* wk = (const float*)d_in[3];
    const float* bk = (const float*)d_in[4];
    const float* wv = (const float*)d_in[5];
    const float* bv = (const float*)d_in[6];
    const float* wo = (const float*)d_in[7];
    const float* bo = (const float*)d_in[8];
    float* out = (float*)d_out;

    float* qkv = nullptr;
    float* att = nullptr;
    cudaGetSymbolAddress((void**)&qkv, g_qkv);
    cudaGetSymbolAddress((void**)&att, g_att);

    cudaFuncSetAttribute(attn_kernel, cudaFuncAttributeMaxDynamicSharedMemorySize, ATTN_SMEM);

    dim3 gg(64, BATCH, 1);
    // Q/K/V projections as 3 launches (places attn at profile slot 4)
    gemm_k<96, 96, false><<<gg, 192>>>(x, 96L * HW, 288L * HW, wq, bq, qkv, qkv);
    gemm_k<96, 96, false><<<gg, 192>>>(x, 96L * HW, 288L * HW, wk, bk, qkv + 96L * HW, qkv);
    gemm_k<96, 96, false><<<gg, 192>>>(x, 96L * HW, 288L * HW, wv, bv, qkv + 192L * HW, qkv);

    // Multi-range local attention: 256 CTAs, 2/SM
    attn_kernel<<<dim3(32, 4, BATCH), 256, ATTN_SMEM>>>();

    // Output projection, K split x2 -> partial slabs in g_qkv (now free)
    float* p0 = qkv;
    float* p1 = qkv + (long)BATCH * 96 * HW;
    gemm_k<288, 144, true><<<dim3(64, BATCH, 2), 192>>>(
        att, 288L * HW, 96L * HW, wo, bo, p0, p1);

    // out = p0 + p1 + bias
    finish_out<<<192, 256>>>(p0, p1, bo, out);
}

// round 7
// speedup vs baseline: 1.1757x; 1.1757x over previous
#include <cuda_runtime.h>
#include <math.h>

#define HW 4096
#define BATCH 2

typedef unsigned long long ull;

// Scratch (device globals — no allocation allowed)
__device__ float g_qkv[BATCH * 288 * HW];  // QKV; later reused as 3 out-proj partial slabs
__device__ float g_att[BATCH * 288 * HW];  // channel = head*72 + range*24 + d

// ---------------------------------------------------------------------------
// f32x2 helpers
// ---------------------------------------------------------------------------
__device__ __forceinline__ ull pk2(float a) {
    ull r; asm("mov.b64 %0, {%1,%1};" : "=l"(r) : "f"(a)); return r;
}
__device__ __forceinline__ ull pkpair(float lo, float hi) {
    ull r; asm("mov.b64 %0, {%1,%2};" : "=l"(r) : "f"(lo), "f"(hi)); return r;
}
__device__ __forceinline__ ull ffma2(ull a, ull b, ull c) {
    ull d; asm("fma.rn.f32x2 %0, %1, %2, %3;" : "=l"(d) : "l"(a), "l"(b), "l"(c)); return d;
}
__device__ __forceinline__ ull add2(ull a, ull b) {
    ull d; asm("add.rn.f32x2 %0, %1, %2;" : "=l"(d) : "l"(a), "l"(b)); return d;
}
__device__ __forceinline__ void upk(ull v, float& lo, float& hi) {
    asm("mov.b64 {%0,%1}, %2;" : "=f"(lo), "=f"(hi) : "l"(v));
}

// ---------------------------------------------------------------------------
// GEMM (f32x2): C[m][pix] = [bias[m] +] sum_{k chunk} W[m][k] * X[k][pix]
// BM=96, BN=128, BK=16, 256 threads, TM=6, TN=8. ~90 regs -> 2 CTAs/SM.
// PARTIAL: z = K-chunk index, C = c_z, raw store.
// else:    z selects (W,bias,C) triple (fused QKV), bias added.
// ---------------------------------------------------------------------------
#define WSTR 100

template <int KTOT, int KCHUNK, bool PARTIAL>
__global__ __launch_bounds__(256, 2) void gemm_k(
    const float* __restrict__ X, long xstride, long cstride,
    const float* w0, const float* w1, const float* w2,
    const float* b0, const float* b1, const float* b2,
    float* c0, float* c1, float* c2)
{
    const int z = blockIdx.z;
    const float* __restrict__ W    = PARTIAL ? w0 : ((z == 0) ? w0 : ((z == 1) ? w1 : w2));
    const float* __restrict__ bias = PARTIAL ? b0 : ((z == 0) ? b0 : ((z == 1) ? b1 : b2));
    float* __restrict__ C = ((z == 0) ? c0 : ((z == 1) ? c1 : c2));
    const int kbeg = PARTIAL ? z * KCHUNK : 0;
    C += (long)blockIdx.y * cstride;
    const float* __restrict__ Xb = X + (long)blockIdx.y * xstride;

    __shared__ float Ws[16][WSTR];
    __shared__ float Xs[16][128];

    const int tid = threadIdx.x;
    const int tx = tid & 15;     // n: 8 cols each (16 groups)
    const int ty = tid >> 4;     // m: 0..15, 6 rows each
    const int n0 = blockIdx.x * 128;

    ull acc[6][4] = {};

    for (int k0 = kbeg; k0 < kbeg + KCHUNK; k0 += 16) {
        // W tile 96x16 -> Ws[kk][m] (transposed); 384 float4 / 256 thr
        for (int idx = tid; idx < 384; idx += 256) {
            int m = idx >> 2, kq = (idx & 3) * 4;
            float4 w = *(const float4*)&W[(long)m * KTOT + k0 + kq];
            Ws[kq + 0][m] = w.x;
            Ws[kq + 1][m] = w.y;
            Ws[kq + 2][m] = w.z;
            Ws[kq + 3][m] = w.w;
        }
        // X tile 16x128; 512 float4 / 256 thr
        #pragma unroll
        for (int i = 0; i < 2; i++) {
            int idx = tid + i * 256;
            int r = idx >> 5, c = (idx & 31) * 4;
            *(float4*)&Xs[r][c] = *(const float4*)&Xb[(long)(k0 + r) * HW + n0 + c];
        }
        __syncthreads();

        #pragma unroll
        for (int kk = 0; kk < 16; kk++) {
            float2 a01 = *(float2*)&Ws[kk][ty * 6];
            float2 a23 = *(float2*)&Ws[kk][ty * 6 + 2];
            float2 a45 = *(float2*)&Ws[kk][ty * 6 + 4];
            ull ad[6] = {pk2(a01.x), pk2(a01.y), pk2(a23.x),
                         pk2(a23.y), pk2(a45.x), pk2(a45.y)};
            ulonglong2 x0 = *(ulonglong2*)&Xs[kk][tx * 8];
            ulonglong2 x1 = *(ulonglong2*)&Xs[kk][tx * 8 + 4];
            ull bq[4] = {x0.x, x0.y, x1.x, x1.y};
            #pragma unroll
            for (int i = 0; i < 6; i++)
                #pragma unroll
                for (int j = 0; j < 4; j++)
                    acc[i][j] = ffma2(ad[i], bq[j], acc[i][j]);
        }
        __syncthreads();
    }

    #pragma unroll
    for (int i = 0; i < 6; i++) {
        int m = ty * 6 + i;
        float bv = PARTIAL ? 0.f : bias[m];
        float4 o0, o1;
        upk(acc[i][0], o0.x, o0.y);
        upk(acc[i][1], o0.z, o0.w);
        upk(acc[i][2], o1.x, o1.y);
        upk(acc[i][3], o1.z, o1.w);
        o0.x += bv; o0.y += bv; o0.z += bv; o0.w += bv;
        o1.x += bv; o1.y += bv; o1.z += bv; o1.w += bv;
        float* cp = &C[(long)m * HW + n0 + tx * 8];
        *(float4*)cp = o0;
        *(float4*)(cp + 4) = o1;
    }
}

// out = p0 + p1 + p2 + bias[m]; 4 float4 per thread for MLP
__global__ __launch_bounds__(256) void finish_out(
    const float* __restrict__ p0, const float* __restrict__ p1,
    const float* __restrict__ p2,
    const float* __restrict__ bo, float* __restrict__ out)
{
    int t = blockIdx.x * 256 + threadIdx.x;   // < 49152
    float4 a[4], c[4], e[4];
    #pragma unroll
    for (int i = 0; i < 4; i++) {
        int idx = t + i * 49152;
        a[i] = ((const float4*)p0)[idx];
        c[i] = ((const float4*)p1)[idx];
        e[i] = ((const float4*)p2)[idx];
    }
    #pragma unroll
    for (int i = 0; i < 4; i++) {
        int idx = t + i * 49152;
        int m = (idx >> 10) % 96;
        float bv = bo[m];
        float4 o;
        o.x = a[i].x + c[i].x + e[i].x + bv;
        o.y = a[i].y + c[i].y + e[i].y + bv;
        o.z = a[i].z + c[i].z + e[i].z + bv;
        o.w = a[i].w + c[i].w + e[i].w + bv;
        ((float4*)out)[idx] = o;
    }
}

// ---------------------------------------------------------------------------
// Attention v5: 8x16 pixel tile per CTA; 256 threads = 128 pixels x 2 roles
// (role 0: dy <= 0, 66 sites; role 1: dy > 0, 55 sites). Single pixel per
// thread, full 24-channel accumulation in f32x2 regs (~120 regs, no spill,
// no shfl). Partials combined via one smem exchange.
// Halo 18x26 x 24 fp32 (K and V), pixel stride 28 floats (conflict-free
// LDS.128). 104.8 KB smem -> 2 CTAs/SM (16 warps); grid 256 = one wave.
// ---------------------------------------------------------------------------
#define PSTR 28
#define HROWS 18
#define HCOLS 26
#define HPX (HROWS * HCOLS)              // 468
#define ATTN_SMEM (2 * HPX * PSTR * 4)   // 104832 B

__global__ __launch_bounds__(256, 2) void attn_kernel()
{
    extern __shared__ float sh[];
    float* Ksh = sh;
    float* Vsh = sh + HPX * PSTR;

    const int head = blockIdx.y;
    const int b = blockIdx.z;
    const int th = (blockIdx.x >> 2) * 8;     // 8 y-tiles
    const int tw = (blockIdx.x & 3) * 16;     // 4 x-tiles
    const int h0 = th - 5, w0 = tw - 5;

    const float* base = g_qkv + (long)b * 288 * HW;
    const float* Kg = base + (96 + head * 24) * HW;
    const float* Vg = base + (192 + head * 24) * HW;

    const int tid = threadIdx.x;

    // ---- halo load: <=2 sites per thread, sweep d ----
    {
        int po[2]; int gi[2]; bool ok[2]; int cnt = 0;
        for (int p = tid; p < HPX; p += 256) {
            int py = p / HCOLS, px = p - py * HCOLS;
            int gy = h0 + py, gx = w0 + px;
            po[cnt] = p * PSTR;
            ok[cnt] = ((unsigned)gy < 64u) && ((unsigned)gx < 64u);
            gi[cnt] = ok[cnt] ? (gy * 64 + gx) : 0;
            cnt++;
        }
        #pragma unroll 4
        for (int d = 0; d < 24; d++) {
            long doff = (long)d * HW;
            #pragma unroll
            for (int n = 0; n < 2; n++) {
                if (n < cnt) {
                    float kv = ok[n] ? Kg[doff + gi[n]] : 0.f;
                    float vv = ok[n] ? Vg[doff + gi[n]] : 0.f;
                    Ksh[po[n] + d] = kv;
                    Vsh[po[n] + d] = vv;
                }
            }
        }
    }
    __syncthreads();

    const int role = tid >> 7;            // 0: dy<=0, 1: dy>0
    const int p = tid & 127;              // pixel id
    const int py = p >> 4, px = p & 15;

    // Q packed pairs, 1/sqrt(24) folded in
    const float* Qg = g_qkv + ((long)b * 288 + head * 24) * HW + (th + py) * 64 + (tw + px);
    ull q2[12];
    #pragma unroll
    for (int j = 0; j < 12; j++) {
        const float sc = 0.2041241452319315f;
        q2[j] = pkpair(Qg[(long)(2 * j) * HW] * sc, Qg[(long)(2 * j + 1) * HW] * sc);
    }

    ull a7[12] = {}, a9[12] = {}, a11[12] = {};
    float l7 = 0.f, l9 = 0.f, l11 = 0.f;
    const int cbase = (py + 5) * HCOLS + (px + 5);

#define BODY(POFF, AC, L) { \
    const ulonglong2* kp = (const ulonglong2*)(Ksh + (cbase + (POFF)) * PSTR); \
    const ulonglong2* vp = (const ulonglong2*)(Vsh + (cbase + (POFF)) * PSTR); \
    ulonglong2 k0 = kp[0], k1 = kp[1], k2 = kp[2]; \
    ulonglong2 k3 = kp[3], k4 = kp[4], k5 = kp[5]; \
    ull sa = 0ULL, sb = 0ULL; \
    sa = ffma2(q2[0], k0.x, sa);  sb = ffma2(q2[1], k0.y, sb); \
    sa = ffma2(q2[2], k1.x, sa);  sb = ffma2(q2[3], k1.y, sb); \
    sa = ffma2(q2[4], k2.x, sa);  sb = ffma2(q2[5], k2.y, sb); \
    sa = ffma2(q2[6], k3.x, sa);  sb = ffma2(q2[7], k3.y, sb); \
    sa = ffma2(q2[8], k4.x, sa);  sb = ffma2(q2[9], k4.y, sb); \
    sa = ffma2(q2[10], k5.x, sa); sb = ffma2(q2[11], k5.y, sb); \
    float x0, x1; upk(add2(sa, sb), x0, x1); \
    float e = __expf(x0 + x1); \
    L += e; ull pe = pk2(e); \
    ulonglong2 v0 = vp[0], v1 = vp[1], v2 = vp[2]; \
    ulonglong2 v3 = vp[3], v4 = vp[4], v5 = vp[5]; \
    AC[0] = ffma2(pe, v0.x, AC[0]);  AC[1]  = ffma2(pe, v0.y, AC[1]); \
    AC[2] = ffma2(pe, v1.x, AC[2]);  AC[3]  = ffma2(pe, v1.y, AC[3]); \
    AC[4] = ffma2(pe, v2.x, AC[4]);  AC[5]  = ffma2(pe, v2.y, AC[5]); \
    AC[6] = ffma2(pe, v3.x, AC[6]);  AC[7]  = ffma2(pe, v3.y, AC[7]); \
    AC[8] = ffma2(pe, v4.x, AC[8]);  AC[9]  = ffma2(pe, v4.y, AC[9]); \
    AC[10] = ffma2(pe, v5.x, AC[10]); AC[11] = ffma2(pe, v5.y, AC[11]); \
}

    if (role == 0) {
        // dy = -5: all ring-11
        #pragma unroll 1
        for (int dx = -5; dx <= 5; dx++) { BODY(-5 * HCOLS + dx, a11, l11) }
        // dy = -4: ring-9 core, ring-11 edges
        BODY(-4 * HCOLS - 5, a11, l11)
        #pragma unroll 1
        for (int dx = -4; dx <= 4; dx++) { BODY(-4 * HCOLS + dx, a9, l9) }
        BODY(-4 * HCOLS + 5, a11, l11)
        // dy = -3..0
        #pragma unroll 1
        for (int dy = -3; dy <= 0; dy++) {
            BODY(dy * HCOLS - 5, a11, l11)
            BODY(dy * HCOLS - 4, a9, l9)
            #pragma unroll 1
            for (int dx = -3; dx <= 3; dx++) { BODY(dy * HCOLS + dx, a7, l7) }
            BODY(dy * HCOLS + 4, a9, l9)
            BODY(dy * HCOLS + 5, a11, l11)
        }
    } else {
        // dy = 1..3
        #pragma unroll 1
        for (int dy = 1; dy <= 3; dy++) {
            BODY(dy * HCOLS - 5, a11, l11)
            BODY(dy * HCOLS - 4, a9, l9)
            #pragma unroll 1
            for (int dx = -3; dx <= 3; dx++) { BODY(dy * HCOLS + dx, a7, l7) }
            BODY(dy * HCOLS + 4, a9, l9)
            BODY(dy * HCOLS + 5, a11, l11)
        }
        // dy = 4
        BODY(4 * HCOLS - 5, a11, l11)
        #pragma unroll 1
        for (int dx = -4; dx <= 4; dx++) { BODY(4 * HCOLS + dx, a9, l9) }
        BODY(4 * HCOLS + 5, a11, l11)
        // dy = 5
        #pragma unroll 1
        for (int dx = -5; dx <= 5; dx++) { BODY(5 * HCOLS + dx, a11, l11) }
    }
#undef BODY

    // ---- combine roles through smem (aliases halo; safe after sync) ----
    __syncthreads();
    ull* red = (ull*)sh;            // 128 px * 40 ull = 40 KB
    if (role == 1) {
        ull* r = red + (size_t)p * 40;
        #pragma unroll
        for (int j = 0; j < 12; j++) {
            r[j] = a7[j]; r[12 + j] = a9[j]; r[24 + j] = a11[j];
        }
        r[36] = pkpair(l7, l9);
        r[37] = pkpair(l11, 0.f);
    }
    __syncthreads();

    if (role == 0) {
        const ull* r = red + (size_t)p * 40;
        #pragma unroll
        for (int j = 0; j < 12; j++) {
            a7[j]  = add2(a7[j],  r[j]);
            a9[j]  = add2(a9[j],  r[12 + j]);
            a11[j] = add2(a11[j], r[24 + j]);
        }
        float t0, t1;
        upk(r[36], t0, t1); l7 += t0; l9 += t1;
        upk(r[37], t0, t1); l11 += t0;

        const float r7  = __fdividef(1.f, l7);
        const float t9  = l7 + l9;
        const float r9  = __fdividef(1.f, t9);
        const float r11 = __fdividef(1.f, t9 + l11);

        float* A = g_att + ((long)b * 288 + head * 72) * HW + (th + py) * 64 + (tw + px);
        #pragma unroll
        for (int j = 0; j < 12; j++) {
            float p70, p71, p90, p91, pb0, pb1;
            upk(a7[j], p70, p71);
            upk(a9[j], p90, p91);
            upk(a11[j], pb0, pb1);
            float s90 = p70 + p90, s91 = p71 + p91;
            float sb0 = s90 + pb0, sb1 = s91 + pb1;
            A[(long)(2 * j) * HW]          = p70 * r7;
            A[(long)(2 * j + 1) * HW]      = p71 * r7;
            A[(long)(24 + 2 * j) * HW]     = s90 * r9;
            A[(long)(24 + 2 * j + 1) * HW] = s91 * r9;
            A[(long)(48 + 2 * j) * HW]     = sb0 * r11;
            A[(long)(48 + 2 * j + 1) * HW] = sb1 * r11;
        }
    }
}

// ---------------------------------------------------------------------------
extern "C" void kernel_launch(void* const* d_in, const int* in_sizes, int n_in,
                              void* d_out, int out_size)
{
    const float* x  = (const float*)d_in[0];
    const float* wq = (const float*)d_in[1];
    const float* bq = (const float*)d_in[2];
    const float* wk = (const float*)d_in[3];
    const float* bk = (const float*)d_in[4];
    const float* wv = (const float*)d_in[5];
    const float* bv = (const float*)d_in[6];
    const float* wo = (const float*)d_in[7];
    const float* bo = (const float*)d_in[8];
    float* out = (float*)d_out;

    float* qkv = nullptr;
    float* att = nullptr;
    cudaGetSymbolAddress((void**)&qkv, g_qkv);
    cudaGetSymbolAddress((void**)&att, g_att);

    cudaFuncSetAttribute(attn_kernel, cudaFuncAttributeMaxDynamicSharedMemorySize, ATTN_SMEM);

    // Fused QKV: grid (4096/128, 2, 3) = 192 CTAs, 2/SM, 16 warps/SM
    gemm_k<96, 96, false><<<dim3(32, BATCH, 3), 256>>>(
        x, 96L * HW, 288L * HW,
        wq, wk, wv, bq, bk, bv,
        qkv, qkv + 96L * HW, qkv + 192L * HW);

    // Multi-range local attention: 256 CTAs, 2/SM (104.8 KB smem each)
    attn_kernel<<<dim3(32, 4, BATCH), 256, ATTN_SMEM>>>();

    // Output projection, K split x3 (96 each) -> 192 CTAs; partials in g_qkv
    float* p0 = qkv;
    float* p1 = qkv + (long)BATCH * 96 * HW;
    float* p2 = qkv + (long)2 * BATCH * 96 * HW;
    gemm_k<288, 96, true><<<dim3(32, BATCH, 3), 256>>>(
        att, 288L * HW, 96L * HW,
        wo, wo, wo, bo, bo, bo,
        p0, p1, p2);

    // out = p0 + p1 + p2 + bias
    finish_out<<<192, 256>>>(p0, p1, p2, bo, out);
}

// round 8
// speedup vs baseline: 1.4270x; 1.2137x over previous
#include <cuda_runtime.h>
#include <math.h>

#define HW 4096
#define BATCH 2

typedef unsigned long long ull;

// Scratch (device globals — no allocation allowed)
__device__ float g_qkv[BATCH * 288 * HW];  // QKV; later reused as out-proj partial slabs
__device__ float g_att[BATCH * 288 * HW];  // channel = head*72 + range*24 + d
__device__ float g_lex[BATCH * 4 * HW];    // per-(b,head,px) boundary l exchange

// ---------------------------------------------------------------------------
// f32x2 helpers
// ---------------------------------------------------------------------------
__device__ __forceinline__ ull pk2(float a) {
    ull r; asm("mov.b64 %0, {%1,%1};" : "=l"(r) : "f"(a)); return r;
}
__device__ __forceinline__ ull pkpair(float lo, float hi) {
    ull r; asm("mov.b64 %0, {%1,%2};" : "=l"(r) : "f"(lo), "f"(hi)); return r;
}
__device__ __forceinline__ ull ffma2(ull a, ull b, ull c) {
    ull d; asm("fma.rn.f32x2 %0, %1, %2, %3;" : "=l"(d) : "l"(a), "l"(b), "l"(c)); return d;
}
__device__ __forceinline__ ull add2(ull a, ull b) {
    ull d; asm("add.rn.f32x2 %0, %1, %2;" : "=l"(d) : "l"(a), "l"(b)); return d;
}
__device__ __forceinline__ void upk(ull v, float& lo, float& hi) {
    asm("mov.b64 {%0,%1}, %2;" : "=f"(lo), "=f"(hi) : "l"(v));
}

// ---------------------------------------------------------------------------
// GEMM (f32x2): C[m][pix] = [bias[m] +] sum_{k in chunk} W[m][k] * X[k][pix]
// BM=96, BN=64, BK=16, 128 threads, TM=6, TN=8.  (R5 measured config)
// ---------------------------------------------------------------------------
#define WSTR 102

template <int KTOT, int KCHUNK, bool PARTIAL>
__global__ __launch_bounds__(128) void gemm_k(
    const float* __restrict__ X, long xstride, long cstride,
    const float* w0, const float* w1, const float* w2,
    const float* b0, const float* b1, const float* b2,
    float* c0, float* c1, float* c2)
{
    const int z = blockIdx.z;
    const float* __restrict__ W;
    const float* __restrict__ bias;
    float* __restrict__ C;
    int kbeg;
    if (PARTIAL) {
        W = w0; bias = b0;
        C = (z == 0) ? c0 : c1;
        kbeg = z * KCHUNK;
    } else {
        W    = (z == 0) ? w0 : ((z == 1) ? w1 : w2);
        bias = (z == 0) ? b0 : ((z == 1) ? b1 : b2);
        C    = (z == 0) ? c0 : ((z == 1) ? c1 : c2);
        kbeg = 0;
    }
    C += (long)blockIdx.y * cstride;
    const float* __restrict__ Xb = X + (long)blockIdx.y * xstride;

    __shared__ float Ws[16][WSTR];
    __shared__ float Xs[16][64];

    const int tid = threadIdx.x;
    const int tx = tid & 7;
    const int ty = tid >> 3;
    const int n0 = blockIdx.x * 64;

    ull acc[6][4] = {};

    for (int k0 = kbeg; k0 < kbeg + KCHUNK; k0 += 16) {
        #pragma unroll
        for (int i = 0; i < 3; i++) {
            int idx = tid + i * 128;
            int m = idx >> 2, kq = (idx & 3) * 4;
            float4 w = *(const float4*)&W[(long)m * KTOT + k0 + kq];
            Ws[kq + 0][m] = w.x;
            Ws[kq + 1][m] = w.y;
            Ws[kq + 2][m] = w.z;
            Ws[kq + 3][m] = w.w;
        }
        #pragma unroll
        for (int i = 0; i < 2; i++) {
            int idx = tid + i * 128;
            int r = idx >> 4, c = (idx & 15) * 4;
            *(float4*)&Xs[r][c] = *(const float4*)&Xb[(long)(k0 + r) * HW + n0 + c];
        }
        __syncthreads();

        #pragma unroll
        for (int kk = 0; kk < 16; kk++) {
            float2 a01 = *(float2*)&Ws[kk][ty * 6];
            float2 a23 = *(float2*)&Ws[kk][ty * 6 + 2];
            float2 a45 = *(float2*)&Ws[kk][ty * 6 + 4];
            ull ad[6] = {pk2(a01.x), pk2(a01.y), pk2(a23.x),
                         pk2(a23.y), pk2(a45.x), pk2(a45.y)};
            ulonglong2 x0 = *(ulonglong2*)&Xs[kk][tx * 8];
            ulonglong2 x1 = *(ulonglong2*)&Xs[kk][tx * 8 + 4];
            ull bq[4] = {x0.x, x0.y, x1.x, x1.y};
            #pragma unroll
            for (int i = 0; i < 6; i++)
                #pragma unroll
                for (int j = 0; j < 4; j++)
                    acc[i][j] = ffma2(ad[i], bq[j], acc[i][j]);
        }
        __syncthreads();
    }

    #pragma unroll
    for (int i = 0; i < 6; i++) {
        int m = ty * 6 + i;
        float bv = PARTIAL ? 0.f : bias[m];
        float4 o0, o1;
        upk(acc[i][0], o0.x, o0.y);
        upk(acc[i][1], o0.z, o0.w);
        upk(acc[i][2], o1.x, o1.y);
        upk(acc[i][3], o1.z, o1.w);
        o0.x += bv; o0.y += bv; o0.z += bv; o0.w += bv;
        o1.x += bv; o1.y += bv; o1.z += bv; o1.w += bv;
        float* cp = &C[(long)m * HW + n0 + tx * 8];
        *(float4*)cp = o0;
        *(float4*)(cp + 4) = o1;
    }
}

// out = p0 + p1 + bias[m]  (R5 measured config)
__global__ __launch_bounds__(256) void finish_out(
    const float* __restrict__ p0, const float* __restrict__ p1,
    const float* __restrict__ bo, float* __restrict__ out)
{
    int idx = blockIdx.x * 256 + threadIdx.x;
    int m = (idx >> 10) % 96;
    float bv = bo[m];
    float4 a = ((const float4*)p0)[idx];
    float4 b = ((const float4*)p1)[idx];
    float4 o;
    o.x = a.x + b.x + bv;
    o.y = a.y + b.y + bv;
    o.z = a.z + b.z + bv;
    o.w = a.w + b.w + bv;
    ((float4*)out)[idx] = o;
}

// ---------------------------------------------------------------------------
// Attention v6: 8x16 tile, 256 threads = 128 px x 2 roles (dy<=0 / dy>0).
// ROLLING ACCUMULATOR: sites processed ring-by-ring (7-core, 9-ring, 11-ring)
// into ONE 12-ull f32x2 accumulator; at each ring boundary role 1 stashes its
// unnormalized partial into the output slab (gmem) + l into g_lex, role 0
// absorbs it, normalizes (l is fully known at the boundary) and writes the
// final range output. Registers: acc 24 + q 24 + temps => ~110, real
// pipelining headroom under the 128-reg / 2-CTA budget.
// Halo 18x26 x 24 fp32, PSTR=28 (16B-aligned conflict-free LDS.128).
// 104.8 KB smem -> 2 CTAs/SM; grid 256 CTAs.
// ---------------------------------------------------------------------------
#define PSTR 28
#define HROWS 18
#define HCOLS 26
#define HPX (HROWS * HCOLS)              // 468
#define ATTN_SMEM (2 * HPX * PSTR * 4)   // 104832 B

__global__ __launch_bounds__(256, 2) void attn_kernel()
{
    extern __shared__ float sh[];
    float* Ksh = sh;
    float* Vsh = sh + HPX * PSTR;

    const int head = blockIdx.y;
    const int b = blockIdx.z;
    const int th = (blockIdx.x >> 2) * 8;
    const int tw = (blockIdx.x & 3) * 16;
    const int h0 = th - 5, w0 = tw - 5;

    const float* base = g_qkv + (long)b * 288 * HW;
    const float* Kg = base + (96 + head * 24) * HW;
    const float* Vg = base + (192 + head * 24) * HW;

    const int tid = threadIdx.x;

    // ---- halo load: <=2 sites per thread, sweep d ----
    {
        int po[2]; int gi[2]; bool ok[2]; int cnt = 0;
        for (int p = tid; p < HPX; p += 256) {
            int py = p / HCOLS, px = p - py * HCOLS;
            int gy = h0 + py, gx = w0 + px;
            po[cnt] = p * PSTR;
            ok[cnt] = ((unsigned)gy < 64u) && ((unsigned)gx < 64u);
            gi[cnt] = ok[cnt] ? (gy * 64 + gx) : 0;
            cnt++;
        }
        #pragma unroll 4
        for (int d = 0; d < 24; d++) {
            long doff = (long)d * HW;
            #pragma unroll
            for (int n = 0; n < 2; n++) {
                if (n < cnt) {
                    float kv = ok[n] ? Kg[doff + gi[n]] : 0.f;
                    float vv = ok[n] ? Vg[doff + gi[n]] : 0.f;
                    Ksh[po[n] + d] = kv;
                    Vsh[po[n] + d] = vv;
                }
            }
        }
    }
    __syncthreads();

    const int role = tid >> 7;            // 0: dy<=0, 1: dy>0
    const int p = tid & 127;
    const int py = p >> 4, px = p & 15;

    // Q packed pairs, 1/sqrt(24) folded in
    const float* Qg = g_qkv + ((long)b * 288 + head * 24) * HW + (th + py) * 64 + (tw + px);
    ull q2[12];
    #pragma unroll
    for (int j = 0; j < 12; j++) {
        const float sc = 0.2041241452319315f;
        q2[j] = pkpair(Qg[(long)(2 * j) * HW] * sc, Qg[(long)(2 * j + 1) * HW] * sc);
    }

    ull acc[12] = {};
    float l = 0.f;
    const int cbase = (py + 5) * HCOLS + (px + 5);

    float* A = g_att + ((long)b * 288 + head * 72) * HW + (th + py) * 64 + (tw + px);
    const int lidx = ((b * 4 + head) * HW) + (th + py) * 64 + (tw + px);

#define BODY(POFF) { \
    const ulonglong2* kp = (const ulonglong2*)(Ksh + (cbase + (POFF)) * PSTR); \
    const ulonglong2* vp = (const ulonglong2*)(Vsh + (cbase + (POFF)) * PSTR); \
    ulonglong2 k0 = kp[0], k1 = kp[1], k2 = kp[2]; \
    ulonglong2 k3 = kp[3], k4 = kp[4], k5 = kp[5]; \
    ull sa = 0ULL, sb = 0ULL; \
    sa = ffma2(q2[0], k0.x, sa);  sb = ffma2(q2[1], k0.y, sb); \
    sa = ffma2(q2[2], k1.x, sa);  sb = ffma2(q2[3], k1.y, sb); \
    sa = ffma2(q2[4], k2.x, sa);  sb = ffma2(q2[5], k2.y, sb); \
    sa = ffma2(q2[6], k3.x, sa);  sb = ffma2(q2[7], k3.y, sb); \
    sa = ffma2(q2[8], k4.x, sa);  sb = ffma2(q2[9], k4.y, sb); \
    sa = ffma2(q2[10], k5.x, sa); sb = ffma2(q2[11], k5.y, sb); \
    float x0, x1; upk(add2(sa, sb), x0, x1); \
    float e = __expf(x0 + x1); \
    l += e; ull pe = pk2(e); \
    ulonglong2 v0 = vp[0], v1 = vp[1], v2 = vp[2]; \
    ulonglong2 v3 = vp[3], v4 = vp[4], v5 = vp[5]; \
    acc[0] = ffma2(pe, v0.x, acc[0]);   acc[1]  = ffma2(pe, v0.y, acc[1]); \
    acc[2] = ffma2(pe, v1.x, acc[2]);   acc[3]  = ffma2(pe, v1.y, acc[3]); \
    acc[4] = ffma2(pe, v2.x, acc[4]);   acc[5]  = ffma2(pe, v2.y, acc[5]); \
    acc[6] = ffma2(pe, v3.x, acc[6]);   acc[7]  = ffma2(pe, v3.y, acc[7]); \
    acc[8] = ffma2(pe, v4.x, acc[8]);   acc[9]  = ffma2(pe, v4.y, acc[9]); \
    acc[10] = ffma2(pe, v5.x, acc[10]); acc[11] = ffma2(pe, v5.y, acc[11]); \
}

    // Boundary: role1 stashes unnormalized partial + l into gmem and resets;
    // role0 absorbs, normalizes (l total known), writes final range output,
    // keeps cumulative acc + l for next ring.
#define BOUNDARY(RB) { \
    __syncthreads(); \
    if (role == 1) { \
        _Pragma("unroll") \
        for (int j = 0; j < 12; j++) { \
            float lo, hi; upk(acc[j], lo, hi); \
            A[(long)((RB) + 2 * j) * HW]     = lo; \
            A[(long)((RB) + 2 * j + 1) * HW] = hi; \
            acc[j] = 0ULL; \
        } \
        g_lex[lidx] = l; l = 0.f; \
    } \
    __syncthreads(); \
    if (role == 0) { \
        l += g_lex[lidx]; \
        float rn = __fdividef(1.f, l); \
        _Pragma("unroll") \
        for (int j = 0; j < 12; j++) { \
            float lo, hi; upk(acc[j], lo, hi); \
            lo += A[(long)((RB) + 2 * j) * HW]; \
            hi += A[(long)((RB) + 2 * j + 1) * HW]; \
            acc[j] = pkpair(lo, hi); \
            A[(long)((RB) + 2 * j) * HW]     = lo * rn; \
            A[(long)((RB) + 2 * j + 1) * HW] = hi * rn; \
        } \
    } \
}

    // ============ ring 7 (7x7 core) ============
    if (role == 0) {
        #pragma unroll 1
        for (int dy = -3; dy <= 0; dy++) {
            #pragma unroll 2
            for (int dx = -3; dx <= 3; dx++) { BODY(dy * HCOLS + dx) }
        }
    } else {
        #pragma unroll 1
        for (int dy = 1; dy <= 3; dy++) {
            #pragma unroll 2
            for (int dx = -3; dx <= 3; dx++) { BODY(dy * HCOLS + dx) }
        }
    }
    BOUNDARY(0)

    // ============ ring 9 (max(|dy|,|dx|) == 4) ============
    if (role == 0) {
        #pragma unroll 2
        for (int dx = -4; dx <= 4; dx++) { BODY(-4 * HCOLS + dx) }
        #pragma unroll 1
        for (int dy = -3; dy <= 0; dy++) { BODY(dy * HCOLS - 4) BODY(dy * HCOLS + 4) }
    } else {
        #pragma unroll 2
        for (int dx = -4; dx <= 4; dx++) { BODY(4 * HCOLS + dx) }
        #pragma unroll 1
        for (int dy = 1; dy <= 3; dy++) { BODY(dy * HCOLS - 4) BODY(dy * HCOLS + 4) }
    }
    BOUNDARY(24)

    // ============ ring 11 (max == 5) ============
    if (role == 0) {
        #pragma unroll 2
        for (int dx = -5; dx <= 5; dx++) { BODY(-5 * HCOLS + dx) }
        #pragma unroll 1
        for (int dy = -4; dy <= 0; dy++) { BODY(dy * HCOLS - 5) BODY(dy * HCOLS + 5) }
    } else {
        #pragma unroll 2
        for (int dx = -5; dx <= 5; dx++) { BODY(5 * HCOLS + dx) }
        #pragma unroll 1
        for (int dy = 1; dy <= 4; dy++) { BODY(dy * HCOLS - 5) BODY(dy * HCOLS + 5) }
    }
    BOUNDARY(48)

#undef BODY
#undef BOUNDARY
}

// ---------------------------------------------------------------------------
extern "C" void kernel_launch(void* const* d_in, const int* in_sizes, int n_in,
                              void* d_out, int out_size)
{
    const float* x  = (const float*)d_in[0];
    const float* wq = (const float*)d_in[1];
    const float* bq = (const float*)d_in[2];
    const float* wk = (const float*)d_in[3];
    const float* bk = (const float*)d_in[4];
    const float* wv = (const float*)d_in[5];
    const float* bv = (const float*)d_in[6];
    const float* wo = (const float*)d_in[7];
    const float* bo = (const float*)d_in[8];
    float* out = (float*)d_out;

    float* qkv = nullptr;
    float* att = nullptr;
    cudaGetSymbolAddress((void**)&qkv, g_qkv);
    cudaGetSymbolAddress((void**)&att, g_att);

    cudaFuncSetAttribute(attn_kernel, cudaFuncAttributeMaxDynamicSharedMemorySize, ATTN_SMEM);

    // Fused QKV: grid (4096/64, 2, 3) = 384 CTAs (R5 config)
    gemm_k<96, 96, false><<<dim3(64, BATCH, 3), 128>>>(
        x, 96L * HW, 288L * HW,
        wq, wk, wv, bq, bk, bv,
        qkv, qkv + 96L * HW, qkv + 192L * HW);

    // Multi-range local attention: 256 CTAs, 2/SM, rolling accumulator
    attn_kernel<<<dim3(32, 4, BATCH), 256, ATTN_SMEM>>>();

    // Output projection, K split x2 -> partial slabs in g_qkv (R5 config)
    float* p0 = qkv;
    float* p1 = qkv + (long)BATCH * 96 * HW;
    gemm_k<288, 144, true><<<dim3(64, BATCH, 2), 128>>>(
        att, 288L * HW, 96L * HW,
        wo, wo, wo, bo, bo, bo,
        p0, p1, p1);

    // out = p0 + p1 + bias
    finish_out<<<768, 256>>>(p0, p1, bo, out);
}